// round 11
// baseline (speedup 1.0000x reference)
#include <cuda_runtime.h>
#include <cstdint>

#define NTOT 32768
#define FDIM 128
#define EMBD 32
#define NG   32
#define NPG  1024
#define OFF_SRC 1048576u
#define OFF_DST 34603008u
#define OFF_EW  68157440u

__device__ float g_xgT[NG * EMBD * NPG];   // [g][k][i]
__device__ float g_sq[NTOT];
__device__ float g_stats[33];              // [0..31]=centroid, [32]=scale

// ---------------------------------------------------------------------------
__device__ __forceinline__ unsigned long long pack2(float lo, float hi) {
    unsigned long long r;
    asm("mov.b64 %0, {%1, %2};" : "=l"(r) : "f"(lo), "f"(hi));
    return r;
}
__device__ __forceinline__ void unpack2(unsigned long long v, float& lo, float& hi) {
    asm("mov.b64 {%0, %1}, %2;" : "=f"(lo), "=f"(hi) : "l"(v));
}
__device__ __forceinline__ unsigned long long ffma2(unsigned long long a,
                                                    unsigned long long b,
                                                    unsigned long long c) {
    unsigned long long d;
    asm("fma.rn.f32x2 %0, %1, %2, %3;" : "=l"(d) : "l"(a), "l"(b), "l"(c));
    return d;
}
__device__ __forceinline__ void st_cs(float* p, float4 v) {
    asm volatile("st.global.cs.v4.f32 [%0], {%1,%2,%3,%4};"
                 :: "l"(p), "f"(v.x), "f"(v.y), "f"(v.z), "f"(v.w) : "memory");
}

// ---------------------------------------------------------------------------
// K1 v3: xe = x @ W. 128 rows/block, k in 4 chunks of 32. (proven R8)
// ---------------------------------------------------------------------------
__global__ __launch_bounds__(256) void k1_gemm(const float* __restrict__ x,
                                               const float* __restrict__ W,
                                               float* __restrict__ xe) {
    __shared__ float xsh[128 * 36];
    __shared__ float wsh[2][32 * 32];
    const int t = threadIdx.x;
    const int row0 = blockIdx.x * 128;
    const int tx = t & 7;
    const int ty = t >> 3;

    unsigned long long acc[4][2];
#pragma unroll
    for (int i = 0; i < 4; i++) { acc[i][0] = 0ull; acc[i][1] = 0ull; }

#pragma unroll
    for (int h = 0; h < 4; h++) {
        __syncthreads();
        for (int e = t; e < 1024; e += 256) {
            const int r = e >> 3, c = e & 7;
            *(float4*)&xsh[r * 36 + c * 4] =
                *(const float4*)(x + (size_t)(row0 + r) * FDIM + h * 32 + c * 4);
        }
        for (int e = t; e < 256; e += 256) {
            const int k = e >> 3, d = e & 7;
            *(float4*)&wsh[h & 1][k * 32 + d * 4] =
                *(const float4*)(W + (size_t)(h * 32 + k) * EMBD + d * 4);
        }
        __syncthreads();
#pragma unroll 8
        for (int k = 0; k < 32; k++) {
            const ulonglong2 wp = *(const ulonglong2*)&wsh[h & 1][k * 32 + tx * 4];
#pragma unroll
            for (int i = 0; i < 4; i++) {
                const float xv = xsh[(ty + 32 * i) * 36 + k];
                const unsigned long long xd = pack2(xv, xv);
                acc[i][0] = ffma2(xd, wp.x, acc[i][0]);
                acc[i][1] = ffma2(xd, wp.y, acc[i][1]);
            }
        }
    }
#pragma unroll
    for (int i = 0; i < 4; i++) {
        float o0, o1, o2, o3;
        unpack2(acc[i][0], o0, o1);
        unpack2(acc[i][1], o2, o3);
        *(float4*)&xe[(size_t)(row0 + ty + 32 * i) * EMBD + tx * 4] =
            make_float4(o0, o1, o2, o3);
    }
}

// ---------------------------------------------------------------------------
// K2: centroid + scale. (proven)
// ---------------------------------------------------------------------------
__global__ __launch_bounds__(1024) void k2_stats(const float* __restrict__ xe) {
    __shared__ float part[32 * 32];
    __shared__ float cent[EMBD];
    const int t = threadIdx.x;
    const int w = t >> 5, l = t & 31;

    float v[EMBD];
#pragma unroll
    for (int q = 0; q < 8; q++) {
        const float4 f = ((const float4*)(xe + (size_t)t * EMBD))[q];
        v[4 * q] = f.x; v[4 * q + 1] = f.y; v[4 * q + 2] = f.z; v[4 * q + 3] = f.w;
    }
#pragma unroll
    for (int d = 0; d < EMBD; d++) {
        float s = v[d];
#pragma unroll
        for (int o = 16; o; o >>= 1) s += __shfl_xor_sync(0xffffffffu, s, o);
        if (l == 0) part[w * 32 + d] = s;
    }
    __syncthreads();
    if (w == 0) {
        float s = 0.f;
#pragma unroll
        for (int b = 0; b < 32; b++) s += part[b * 32 + l];
        const float c = s * (1.0f / 1024.0f);
        cent[l] = c;
        g_stats[l] = c;
    }
    __syncthreads();
#pragma unroll
    for (int d = 0; d < EMBD; d++) {
        float m = fabsf(v[d] - cent[d]);
#pragma unroll
        for (int o = 16; o; o >>= 1) m = fmaxf(m, __shfl_xor_sync(0xffffffffu, m, o));
        if (l == 0) part[w * 32 + d] = m;
    }
    __syncthreads();
    if (w == 0) {
        float m = 0.f;
#pragma unroll
        for (int b = 0; b < 32; b++) m = fmaxf(m, part[b * 32 + l]);
#pragma unroll
        for (int o = 16; o; o >>= 1) m = fmaxf(m, __shfl_xor_sync(0xffffffffu, m, o));
        if (l == 0) g_stats[32] = 0.9f / m;
    }
}

// ---------------------------------------------------------------------------
// K3: normalize -> transposed per-graph layout + row norms (proven)
// ---------------------------------------------------------------------------
__global__ __launch_bounds__(256) void k3_norm(const float* __restrict__ xe) {
    const int i = blockIdx.x * 256 + threadIdx.x;
    const float scale = g_stats[32];
    const int g  = i >> 10;
    const int il = i & 1023;
    const float* row = xe + (size_t)i * EMBD;
    float* dstb = g_xgT + (size_t)g * (EMBD * NPG) + il;
    float s = 0.f;
#pragma unroll
    for (int k = 0; k < EMBD; k++) {
        const float v = (row[k] - g_stats[k]) * scale;
        dstb[k * NPG] = v;
        s = fmaf(v, v, s);
    }
    g_sq[i] = s;
}

// ---------------------------------------------------------------------------
// K4 v3: SYMMETRIC. Upper-triangular 128x128 tile pairs: 36 tiles/graph.
// 512 threads, 4x8 outputs/thread. Off-diagonal tiles written twice:
// direct at (I,J), mirrored at (J,I) via padded smem transpose (stride 129).
// FMA work = 0.56x of full grid; store volume unchanged.
// ---------------------------------------------------------------------------
__global__ __launch_bounds__(512, 2) void k4_pair(float* __restrict__ out,
                                                  const float* __restrict__ tptr,
                                                  const float* __restrict__ thptr) {
    __shared__ __align__(16) unsigned char sbuf[64 * 129 * 4];  // 33024 B union
    __shared__ float sqi[128], sqj[128];
    float* const xiT   = (float*)sbuf;             // [32][128] 16 KB (mainloop)
    float* const xjT   = (float*)(sbuf + 16384);   // [32][128] 16 KB (mainloop)
    float* const trans = (float*)sbuf;             // [64][129] (epilogue)

    const int t = threadIdx.x;
    const int g = blockIdx.z;
    // decode upper-triangular pair (I <= J) from blockIdx.x in [0,36)
    int p = blockIdx.x, I = 0;
    while (p >= 8 - I) { p -= 8 - I; I++; }
    const int J = I + p;
    const int i0 = I * 128, j0 = J * 128;

    const int tx = t & 15, ty = t >> 4;
    const int isub = ty * 4, jsub = tx * 8;

    // ---- stage tiles ----
    const float* base = g_xgT + (size_t)g * (EMBD * NPG);
    for (int e = t; e < 1024; e += 512) {
        const int k = e >> 5, c = e & 31;
        ((float4*)xiT)[e] = *(const float4*)(base + k * NPG + i0 + c * 4);
        ((float4*)xjT)[e] = *(const float4*)(base + k * NPG + j0 + c * 4);
    }
    if (t < 128)        sqi[t]       = g_sq[g * NPG + i0 + t];
    else if (t < 256)   sqj[t - 128] = g_sq[g * NPG + j0 + (t - 128)];
    __syncthreads();

    // ---- mainloop: 4x8 per thread, f32x2 ----
    unsigned long long acc[4][4];
#pragma unroll
    for (int r = 0; r < 4; r++)
#pragma unroll
        for (int c = 0; c < 4; c++) acc[r][c] = 0ull;

#pragma unroll
    for (int k = 0; k < EMBD; k++) {
        const ulonglong2 b01 = *(const ulonglong2*)&xjT[k * 128 + jsub];
        const ulonglong2 b23 = *(const ulonglong2*)&xjT[k * 128 + jsub + 4];
        const float4 a = *(const float4*)&xiT[k * 128 + isub];
        const float av[4] = {a.x, a.y, a.z, a.w};
#pragma unroll
        for (int r = 0; r < 4; r++) {
            const unsigned long long ad = pack2(av[r], av[r]);
            acc[r][0] = ffma2(ad, b01.x, acc[r][0]);
            acc[r][1] = ffma2(ad, b01.y, acc[r][1]);
            acc[r][2] = ffma2(ad, b23.x, acc[r][2]);
            acc[r][3] = ffma2(ad, b23.y, acc[r][3]);
        }
    }

    // ---- sigmoid ----
    const float temp = *tptr;
    const float athr = fabsf(*thptr);
    float sjv[8];
#pragma unroll
    for (int c = 0; c < 8; c++) sjv[c] = sqj[jsub + c];

    float Av[4][8];
#pragma unroll
    for (int r = 0; r < 4; r++) {
        const float si = sqi[isub + r];
#pragma unroll
        for (int c = 0; c < 4; c++) {
            float d0, d1;
            unpack2(acc[r][c], d0, d1);
            const float D0 = fmaxf(si + sjv[2 * c]     - 2.0f * d0, 0.0f);
            const float D1 = fmaxf(si + sjv[2 * c + 1] - 2.0f * d1, 0.0f);
            Av[r][2 * c]     = __fdividef(1.0f, 1.0f + __expf(temp * (D0 - athr)));
            Av[r][2 * c + 1] = __fdividef(1.0f, 1.0f + __expf(temp * (D1 - athr)));
        }
    }

    // ---- direct stores at (I,J) ----
    {
        const size_t ebase = (size_t)g * ((size_t)NPG * NPG)
                           + (size_t)(i0 + isub) * NPG + (size_t)(j0 + jsub);
        const float jb = (float)(g * NPG + j0 + jsub);
        const float4 dstA = make_float4(jb, jb + 1.f, jb + 2.f, jb + 3.f);
        const float4 dstB = make_float4(jb + 4.f, jb + 5.f, jb + 6.f, jb + 7.f);
#pragma unroll
        for (int r = 0; r < 4; r++) {
            const size_t eidx = ebase + (size_t)r * NPG;
            st_cs(out + OFF_EW + eidx,     make_float4(Av[r][0], Av[r][1], Av[r][2], Av[r][3]));
            st_cs(out + OFF_EW + eidx + 4, make_float4(Av[r][4], Av[r][5], Av[r][6], Av[r][7]));
            const float fs = (float)(g * NPG + i0 + isub + r);
            const float4 s4 = make_float4(fs, fs, fs, fs);
            st_cs(out + OFF_SRC + eidx,     s4);
            st_cs(out + OFF_SRC + eidx + 4, s4);
            st_cs(out + OFF_DST + eidx,     dstA);
            st_cs(out + OFF_DST + eidx + 4, dstB);
        }
    }

    // ---- mirror stores at (J,I) via smem transpose ----
    if (I != J) {
        const int jj = t >> 2, q = t & 3;     // row within mirror tile, col quarter
        const size_t mrow = (size_t)g * ((size_t)NPG * NPG)
                          + (size_t)(j0 + jj) * NPG;
        const float fsm = (float)(g * NPG + j0 + jj);
        const float4 sm4 = make_float4(fsm, fsm, fsm, fsm);

#pragma unroll
        for (int c = 0; c < 2; c++) {          // two 64-row chunks of i
            __syncthreads();                   // prior reads (tiles / chunk0) done
            if ((isub >> 6) == c) {
#pragma unroll
                for (int r = 0; r < 4; r++)
#pragma unroll
                    for (int cc = 0; cc < 8; cc++)
                        trans[(isub + r - c * 64) * 129 + jsub + cc] = Av[r][cc];
            }
            __syncthreads();
            // read transposed: 16 cols of i for this thread's mirror row
            float4 v[4];
#pragma unroll
            for (int s = 0; s < 16; s++)
                ((float*)v)[s] = trans[(q * 16 + s) * 129 + jj];
            const size_t mcol = mrow + (size_t)(i0 + c * 64 + q * 16);
            st_cs(out + OFF_EW + mcol,      v[0]);
            st_cs(out + OFF_EW + mcol + 4,  v[1]);
            st_cs(out + OFF_EW + mcol + 8,  v[2]);
            st_cs(out + OFF_EW + mcol + 12, v[3]);
            st_cs(out + OFF_SRC + mcol,      sm4);
            st_cs(out + OFF_SRC + mcol + 4,  sm4);
            st_cs(out + OFF_SRC + mcol + 8,  sm4);
            st_cs(out + OFF_SRC + mcol + 12, sm4);
            // dst carries the global graph offset g*NPG (fixed in R10)
            const float ib = (float)(g * NPG + i0 + c * 64 + q * 16);
            st_cs(out + OFF_DST + mcol,      make_float4(ib, ib + 1.f, ib + 2.f, ib + 3.f));
            st_cs(out + OFF_DST + mcol + 4,  make_float4(ib + 4.f, ib + 5.f, ib + 6.f, ib + 7.f));
            st_cs(out + OFF_DST + mcol + 8,  make_float4(ib + 8.f, ib + 9.f, ib + 10.f, ib + 11.f));
            st_cs(out + OFF_DST + mcol + 12, make_float4(ib + 12.f, ib + 13.f, ib + 14.f, ib + 15.f));
        }
    }
}

// ---------------------------------------------------------------------------
extern "C" void kernel_launch(void* const* d_in, const int* in_sizes, int n_in,
                              void* d_out, int out_size) {
    const float* x     = (const float*)d_in[0];
    const float* W     = (const float*)d_in[1];
    const float* tptr  = (const float*)d_in[2];
    const float* thptr = (const float*)d_in[3];
    float* out = (float*)d_out;

    k1_gemm<<<NTOT / 128, 256>>>(x, W, out);
    k2_stats<<<1, 1024>>>(out);
    k3_norm<<<NTOT / 256, 256>>>(out);
    k4_pair<<<dim3(36, 1, NG), 512>>>(out, tptr, thptr);
}

// round 12
// speedup vs baseline: 1.5280x; 1.5280x over previous
#include <cuda_runtime.h>
#include <cstdint>

#define NTOT 32768
#define FDIM 128
#define EMBD 32
#define NG   32
#define NPG  1024
#define OFF_SRC 1048576u
#define OFF_DST 34603008u
#define OFF_EW  68157440u
#define G_HELPER 9            // graphs [0,9): src/dst written by k1/k3

__device__ float g_xgT[NG * EMBD * NPG];   // [g][k][i]
__device__ float g_sq[NTOT];
__device__ float g_stats[33];              // [0..31]=centroid, [32]=scale

// ---------------------------------------------------------------------------
__device__ __forceinline__ unsigned long long pack2(float lo, float hi) {
    unsigned long long r;
    asm("mov.b64 %0, {%1, %2};" : "=l"(r) : "f"(lo), "f"(hi));
    return r;
}
__device__ __forceinline__ void unpack2(unsigned long long v, float& lo, float& hi) {
    asm("mov.b64 {%0, %1}, %2;" : "=f"(lo), "=f"(hi) : "l"(v));
}
__device__ __forceinline__ unsigned long long ffma2(unsigned long long a,
                                                    unsigned long long b,
                                                    unsigned long long c) {
    unsigned long long d;
    asm("fma.rn.f32x2 %0, %1, %2, %3;" : "=l"(d) : "l"(a), "l"(b), "l"(c));
    return d;
}
__device__ __forceinline__ void st_cs(float* p, float4 v) {
    asm volatile("st.global.cs.v4.f32 [%0], {%1,%2,%3,%4};"
                 :: "l"(p), "f"(v.x), "f"(v.y), "f"(v.z), "f"(v.w) : "memory");
}

// Write float4 #q of the combined src/dst region for graphs [g0, g0+ng).
// Layout: first ng*262144 float4 = src floats, then ng*262144 = dst floats.
__device__ __forceinline__ void write_idx4(float* __restrict__ out,
                                           unsigned q, int g0, int ng) {
    const unsigned half = (unsigned)ng * 262144u;
    if (q < half) {
        const int g = g0 + (int)(q >> 18);
        const unsigned l4 = q & 262143u;          // float4 within graph
        const int r = (int)(l4 >> 8);             // row (256 float4/row)
        const float v = (float)(g * NPG + r);
        st_cs(out + OFF_SRC + (size_t)g * 1048576u + (size_t)l4 * 4,
              make_float4(v, v, v, v));
    } else {
        q -= half;
        const int g = g0 + (int)(q >> 18);
        const unsigned l4 = q & 262143u;
        const int col = (int)(l4 & 255u) * 4;
        const float v = (float)(g * NPG + col);
        st_cs(out + OFF_DST + (size_t)g * 1048576u + (size_t)l4 * 4,
              make_float4(v, v + 1.f, v + 2.f, v + 3.f));
    }
}

// ---------------------------------------------------------------------------
// K1 v3: xe = x @ W (proven R8) + src/dst stores for graphs [0,6).
// ---------------------------------------------------------------------------
__global__ __launch_bounds__(256) void k1_gemm(const float* __restrict__ x,
                                               const float* __restrict__ W,
                                               float* __restrict__ xe) {
    __shared__ float xsh[128 * 36];
    __shared__ float wsh[2][32 * 32];
    const int t = threadIdx.x;
    const int row0 = blockIdx.x * 128;
    const int tx = t & 7;
    const int ty = t >> 3;

    unsigned long long acc[4][2];
#pragma unroll
    for (int i = 0; i < 4; i++) { acc[i][0] = 0ull; acc[i][1] = 0ull; }

#pragma unroll
    for (int h = 0; h < 4; h++) {
        __syncthreads();
        for (int e = t; e < 1024; e += 256) {
            const int r = e >> 3, c = e & 7;
            *(float4*)&xsh[r * 36 + c * 4] =
                *(const float4*)(x + (size_t)(row0 + r) * FDIM + h * 32 + c * 4);
        }
        for (int e = t; e < 256; e += 256) {
            const int k = e >> 3, d = e & 7;
            *(float4*)&wsh[h & 1][k * 32 + d * 4] =
                *(const float4*)(W + (size_t)(h * 32 + k) * EMBD + d * 4);
        }
        __syncthreads();
#pragma unroll 8
        for (int k = 0; k < 32; k++) {
            const ulonglong2 wp = *(const ulonglong2*)&wsh[h & 1][k * 32 + tx * 4];
#pragma unroll
            for (int i = 0; i < 4; i++) {
                const float xv = xsh[(ty + 32 * i) * 36 + k];
                const unsigned long long xd = pack2(xv, xv);
                acc[i][0] = ffma2(xd, wp.x, acc[i][0]);
                acc[i][1] = ffma2(xd, wp.y, acc[i][1]);
            }
        }
    }
#pragma unroll
    for (int i = 0; i < 4; i++) {
        float o0, o1, o2, o3;
        unpack2(acc[i][0], o0, o1);
        unpack2(acc[i][1], o2, o3);
        *(float4*)&xe[(size_t)(row0 + ty + 32 * i) * EMBD + tx * 4] =
            make_float4(o0, o1, o2, o3);
    }

    // ---- offloaded src/dst for graphs [0,6): 6*2*262144 = 3,145,728 float4
    // over 256 blocks * 256 threads = 65536 threads -> 48 each, coalesced.
    {
        const unsigned tid = blockIdx.x * 256u + t;
#pragma unroll
        for (int i = 0; i < 48; i++)
            write_idx4(xe, tid + (unsigned)i * 65536u, 0, 6);
    }
}

// ---------------------------------------------------------------------------
// K2: centroid + scale. (proven)
// ---------------------------------------------------------------------------
__global__ __launch_bounds__(1024) void k2_stats(const float* __restrict__ xe) {
    __shared__ float part[32 * 32];
    __shared__ float cent[EMBD];
    const int t = threadIdx.x;
    const int w = t >> 5, l = t & 31;

    float v[EMBD];
#pragma unroll
    for (int q = 0; q < 8; q++) {
        const float4 f = ((const float4*)(xe + (size_t)t * EMBD))[q];
        v[4 * q] = f.x; v[4 * q + 1] = f.y; v[4 * q + 2] = f.z; v[4 * q + 3] = f.w;
    }
#pragma unroll
    for (int d = 0; d < EMBD; d++) {
        float s = v[d];
#pragma unroll
        for (int o = 16; o; o >>= 1) s += __shfl_xor_sync(0xffffffffu, s, o);
        if (l == 0) part[w * 32 + d] = s;
    }
    __syncthreads();
    if (w == 0) {
        float s = 0.f;
#pragma unroll
        for (int b = 0; b < 32; b++) s += part[b * 32 + l];
        const float c = s * (1.0f / 1024.0f);
        cent[l] = c;
        g_stats[l] = c;
    }
    __syncthreads();
#pragma unroll
    for (int d = 0; d < EMBD; d++) {
        float m = fabsf(v[d] - cent[d]);
#pragma unroll
        for (int o = 16; o; o >>= 1) m = fmaxf(m, __shfl_xor_sync(0xffffffffu, m, o));
        if (l == 0) part[w * 32 + d] = m;
    }
    __syncthreads();
    if (w == 0) {
        float m = 0.f;
#pragma unroll
        for (int b = 0; b < 32; b++) m = fmaxf(m, part[b * 32 + l]);
#pragma unroll
        for (int o = 16; o; o >>= 1) m = fmaxf(m, __shfl_xor_sync(0xffffffffu, m, o));
        if (l == 0) g_stats[32] = 0.9f / m;
    }
}

// ---------------------------------------------------------------------------
// K3: normalize -> transposed layout + row norms (proven)
//     + src/dst stores for graphs [6,9).
// ---------------------------------------------------------------------------
__global__ __launch_bounds__(256) void k3_norm(const float* __restrict__ xe,
                                               float* __restrict__ out) {
    const int i = blockIdx.x * 256 + threadIdx.x;
    const float scale = g_stats[32];
    const int g  = i >> 10;
    const int il = i & 1023;
    const float* row = xe + (size_t)i * EMBD;
    float* dstb = g_xgT + (size_t)g * (EMBD * NPG) + il;
    float s = 0.f;
#pragma unroll
    for (int k = 0; k < EMBD; k++) {
        const float v = (row[k] - g_stats[k]) * scale;
        dstb[k * NPG] = v;
        s = fmaf(v, v, s);
    }
    g_sq[i] = s;

    // ---- offloaded src/dst for graphs [6,9): 3*2*262144 = 1,572,864 float4
    // over 128 blocks * 256 threads = 32768 threads -> 48 each, coalesced.
    {
        const unsigned tid = (unsigned)i;
#pragma unroll
        for (int q = 0; q < 48; q++)
            write_idx4(out, tid + (unsigned)q * 32768u, 6, 3);
    }
}

// ---------------------------------------------------------------------------
// K4: EXACT R8 version; src/dst stores skipped for g < G_HELPER.
// ---------------------------------------------------------------------------
__global__ __launch_bounds__(256, 4) void k4_pair(float* __restrict__ out,
                                                  const float* __restrict__ tptr,
                                                  const float* __restrict__ thptr) {
    __shared__ float xiT[EMBD * 128];   // [k][i] 16 KB
    __shared__ float xjT[EMBD * 64];    // [k][j] 8 KB
    __shared__ float sqi[128], sqj[64];

    const int t  = threadIdx.x;
    const int g  = blockIdx.z;
    const int i0 = blockIdx.y * 128;
    const int j0 = blockIdx.x * 64;
    const float* base = g_xgT + (size_t)g * (EMBD * NPG);

    for (int e = t; e < 1024; e += 256) {
        const int k = e >> 5, c = e & 31;
        ((float4*)xiT)[e] = *(const float4*)(base + k * NPG + i0 + c * 4);
    }
    for (int e = t; e < 512; e += 256) {
        const int k = e >> 4, c = e & 15;
        ((float4*)xjT)[e] = *(const float4*)(base + k * NPG + j0 + c * 4);
    }
    if (t < 128)        sqi[t]       = g_sq[g * NPG + i0 + t];
    else if (t < 192)   sqj[t - 128] = g_sq[g * NPG + j0 + (t - 128)];
    __syncthreads();

    const int ty = t >> 4, tx = t & 15;
    const int isub = ty * 8, jsub = tx * 4;

    unsigned long long acc[8][2];
#pragma unroll
    for (int r = 0; r < 8; r++) { acc[r][0] = 0ull; acc[r][1] = 0ull; }

#pragma unroll
    for (int k = 0; k < EMBD; k++) {
        const float4 A0 = *(const float4*)&xiT[k * 128 + isub];
        const float4 A1 = *(const float4*)&xiT[k * 128 + isub + 4];
        const float4 B  = *(const float4*)&xjT[k * 64 + jsub];
        const unsigned long long bp0 = pack2(B.x, B.y);
        const unsigned long long bp1 = pack2(B.z, B.w);
        const float av[8] = {A0.x, A0.y, A0.z, A0.w, A1.x, A1.y, A1.z, A1.w};
#pragma unroll
        for (int r = 0; r < 8; r++) {
            const unsigned long long as = pack2(av[r], av[r]);
            acc[r][0] = ffma2(as, bp0, acc[r][0]);
            acc[r][1] = ffma2(as, bp1, acc[r][1]);
        }
    }

    const float temp = *tptr;
    const float athr = fabsf(*thptr);
    const float sj0 = sqj[jsub], sj1 = sqj[jsub + 1];
    const float sj2 = sqj[jsub + 2], sj3 = sqj[jsub + 3];
    const float jbasef = (float)(g * NPG + j0 + jsub);
    const float4 dst4 = make_float4(jbasef, jbasef + 1.f, jbasef + 2.f, jbasef + 3.f);
    const bool write_idx = (g >= G_HELPER);

#pragma unroll
    for (int r = 0; r < 8; r++) {
        const int il = isub + r;
        const float si = sqi[il];
        float d0, d1, d2, d3;
        unpack2(acc[r][0], d0, d1);
        unpack2(acc[r][1], d2, d3);
        const float D0 = fmaxf(si + sj0 - 2.0f * d0, 0.0f);
        const float D1 = fmaxf(si + sj1 - 2.0f * d1, 0.0f);
        const float D2 = fmaxf(si + sj2 - 2.0f * d2, 0.0f);
        const float D3 = fmaxf(si + sj3 - 2.0f * d3, 0.0f);
        float4 A4;
        A4.x = __fdividef(1.0f, 1.0f + __expf(temp * (D0 - athr)));
        A4.y = __fdividef(1.0f, 1.0f + __expf(temp * (D1 - athr)));
        A4.z = __fdividef(1.0f, 1.0f + __expf(temp * (D2 - athr)));
        A4.w = __fdividef(1.0f, 1.0f + __expf(temp * (D3 - athr)));

        const size_t eidx = (size_t)g * ((size_t)NPG * NPG)
                          + (size_t)(i0 + il) * NPG + (size_t)(j0 + jsub);
        st_cs(out + OFF_EW + eidx, A4);
        if (write_idx) {
            const float fsrc = (float)(g * NPG + i0 + il);
            st_cs(out + OFF_SRC + eidx, make_float4(fsrc, fsrc, fsrc, fsrc));
            st_cs(out + OFF_DST + eidx, dst4);
        }
    }
}

// ---------------------------------------------------------------------------
extern "C" void kernel_launch(void* const* d_in, const int* in_sizes, int n_in,
                              void* d_out, int out_size) {
    const float* x     = (const float*)d_in[0];
    const float* W     = (const float*)d_in[1];
    const float* tptr  = (const float*)d_in[2];
    const float* thptr = (const float*)d_in[3];
    float* out = (float*)d_out;

    k1_gemm<<<NTOT / 128, 256>>>(x, W, out);
    k2_stats<<<1, 1024>>>(out);
    k3_norm<<<NTOT / 256, 256>>>(out, out);
    k4_pair<<<dim3(16, 8, NG), 256>>>(out, tptr, thptr);
}

// round 15
// speedup vs baseline: 1.5559x; 1.0183x over previous
#include <cuda_runtime.h>
#include <cstdint>

#define NTOT 32768
#define FDIM 128
#define EMBD 32
#define NG   32
#define NPG  1024
#define OFF_SRC 1048576u
#define OFF_DST 34603008u
#define OFF_EW  68157440u
#define G_HELPER 4            // graphs [0,4): src/dst written by k1

__device__ float g_stats[33];   // [0..31]=centroid, [32]=scale

// ---------------------------------------------------------------------------
__device__ __forceinline__ unsigned long long pack2(float lo, float hi) {
    unsigned long long r;
    asm("mov.b64 %0, {%1, %2};" : "=l"(r) : "f"(lo), "f"(hi));
    return r;
}
__device__ __forceinline__ void unpack2(unsigned long long v, float& lo, float& hi) {
    asm("mov.b64 {%0, %1}, %2;" : "=f"(lo), "=f"(hi) : "l"(v));
}
__device__ __forceinline__ unsigned long long ffma2(unsigned long long a,
                                                    unsigned long long b,
                                                    unsigned long long c) {
    unsigned long long d;
    asm("fma.rn.f32x2 %0, %1, %2, %3;" : "=l"(d) : "l"(a), "l"(b), "l"(c));
    return d;
}
__device__ __forceinline__ void st_cs(float* p, float4 v) {
    asm volatile("st.global.cs.v4.f32 [%0], {%1,%2,%3,%4};"
                 :: "l"(p), "f"(v.x), "f"(v.y), "f"(v.z), "f"(v.w) : "memory");
}

// ---------------------------------------------------------------------------
// K1 v3 (proven R8): xe = x @ W + src/dst stores for graphs [0,4) (32 MB).
// Offload stores: straight-line loops, no per-store branch.
// ---------------------------------------------------------------------------
__global__ __launch_bounds__(256) void k1_gemm(const float* __restrict__ x,
                                               const float* __restrict__ W,
                                               float* __restrict__ xe) {
    __shared__ float xsh[128 * 36];
    __shared__ float wsh[2][32 * 32];
    const int t = threadIdx.x;
    const int row0 = blockIdx.x * 128;
    const int tx = t & 7;
    const int ty = t >> 3;

    unsigned long long acc[4][2];
#pragma unroll
    for (int i = 0; i < 4; i++) { acc[i][0] = 0ull; acc[i][1] = 0ull; }

#pragma unroll
    for (int h = 0; h < 4; h++) {
        __syncthreads();
        for (int e = t; e < 1024; e += 256) {
            const int r = e >> 3, c = e & 7;
            *(float4*)&xsh[r * 36 + c * 4] =
                *(const float4*)(x + (size_t)(row0 + r) * FDIM + h * 32 + c * 4);
        }
        for (int e = t; e < 256; e += 256) {
            const int k = e >> 3, d = e & 7;
            *(float4*)&wsh[h & 1][k * 32 + d * 4] =
                *(const float4*)(W + (size_t)(h * 32 + k) * EMBD + d * 4);
        }
        __syncthreads();
#pragma unroll 8
        for (int k = 0; k < 32; k++) {
            const ulonglong2 wp = *(const ulonglong2*)&wsh[h & 1][k * 32 + tx * 4];
#pragma unroll
            for (int i = 0; i < 4; i++) {
                const float xv = xsh[(ty + 32 * i) * 36 + k];
                const unsigned long long xd = pack2(xv, xv);
                acc[i][0] = ffma2(xd, wp.x, acc[i][0]);
                acc[i][1] = ffma2(xd, wp.y, acc[i][1]);
            }
        }
    }
#pragma unroll
    for (int i = 0; i < 4; i++) {
        float o0, o1, o2, o3;
        unpack2(acc[i][0], o0, o1);
        unpack2(acc[i][1], o2, o3);
        *(float4*)&xe[(size_t)(row0 + ty + 32 * i) * EMBD + tx * 4] =
            make_float4(o0, o1, o2, o3);
    }

    // ---- offloaded src/dst for graphs [0,4): 2 regions x 4 MiF4 each ----
    // 1,048,576 float4 per region over 65536 threads -> 16 iterations each.
    {
        const unsigned tid = blockIdx.x * 256u + t;
        // src: value constant per row (256 float4 per row)
#pragma unroll
        for (int i = 0; i < 16; i++) {
            const unsigned q = tid + (unsigned)i * 65536u;   // [0, 2^20)
            const int g = (int)(q >> 18);                    // graph 0..3
            const unsigned l4 = q & 262143u;
            const float v = (float)(g * NPG + (int)(l4 >> 8));
            st_cs(xe + OFF_SRC + (size_t)g * 1048576u + (size_t)l4 * 4,
                  make_float4(v, v, v, v));
        }
        // dst: value = column index
#pragma unroll
        for (int i = 0; i < 16; i++) {
            const unsigned q = tid + (unsigned)i * 65536u;
            const int g = (int)(q >> 18);
            const unsigned l4 = q & 262143u;
            const float v = (float)(g * NPG + (int)(l4 & 255u) * 4);
            st_cs(xe + OFF_DST + (size_t)g * 1048576u + (size_t)l4 * 4,
                  make_float4(v, v + 1.f, v + 2.f, v + 3.f));
        }
    }
}

// ---------------------------------------------------------------------------
// K2: centroid + scale. (proven)
// ---------------------------------------------------------------------------
__global__ __launch_bounds__(1024) void k2_stats(const float* __restrict__ xe) {
    __shared__ float part[32 * 32];
    __shared__ float cent[EMBD];
    const int t = threadIdx.x;
    const int w = t >> 5, l = t & 31;

    float v[EMBD];
#pragma unroll
    for (int q = 0; q < 8; q++) {
        const float4 f = ((const float4*)(xe + (size_t)t * EMBD))[q];
        v[4 * q] = f.x; v[4 * q + 1] = f.y; v[4 * q + 2] = f.z; v[4 * q + 3] = f.w;
    }
#pragma unroll
    for (int d = 0; d < EMBD; d++) {
        float s = v[d];
#pragma unroll
        for (int o = 16; o; o >>= 1) s += __shfl_xor_sync(0xffffffffu, s, o);
        if (l == 0) part[w * 32 + d] = s;
    }
    __syncthreads();
    if (w == 0) {
        float s = 0.f;
#pragma unroll
        for (int b = 0; b < 32; b++) s += part[b * 32 + l];
        const float c = s * (1.0f / 1024.0f);
        cent[l] = c;
        g_stats[l] = c;
    }
    __syncthreads();
#pragma unroll
    for (int d = 0; d < EMBD; d++) {
        float m = fabsf(v[d] - cent[d]);
#pragma unroll
        for (int o = 16; o; o >>= 1) m = fmaxf(m, __shfl_xor_sync(0xffffffffu, m, o));
        if (l == 0) part[w * 32 + d] = m;
    }
    __syncthreads();
    if (w == 0) {
        float m = 0.f;
#pragma unroll
        for (int b = 0; b < 32; b++) m = fmaxf(m, part[b * 32 + l]);
#pragma unroll
        for (int o = 16; o; o >>= 1) m = fmaxf(m, __shfl_xor_sync(0xffffffffu, m, o));
        if (l == 0) g_stats[32] = 0.9f / m;
    }
}

// ---------------------------------------------------------------------------
// K4: fused normalize (R5-validated staging) + R8-proven mainloop/epilogue.
// 128x64 tiles, 256 threads, 8x4/thread. src/dst skipped for g < G_HELPER.
// ---------------------------------------------------------------------------
__global__ __launch_bounds__(256, 4) void k4_pair(const float* __restrict__ xe,
                                                  float* __restrict__ out,
                                                  const float* __restrict__ tptr,
                                                  const float* __restrict__ thptr) {
    __shared__ float xiT[EMBD * 128];   // [k][i] 16 KB
    __shared__ float xjT[EMBD * 64];    // [k][j] 8 KB
    __shared__ float psqi[256];
    __shared__ float psqj[128];
    __shared__ float sqi[128], sqj[64];

    const int t  = threadIdx.x;
    const int g  = blockIdx.z;
    const int i0 = blockIdx.y * 128;
    const int j0 = blockIdx.x * 64;
    const float scale = g_stats[32];

    // ---- fused staging from xe: thread t -> row r=t>>1, dim-half h=t&1 ----
    {
        const int r = t >> 1, h = t & 1;
        const float* xrow = xe + (size_t)(g * NPG + i0 + r) * EMBD + h * 16;
        float ps = 0.f;
#pragma unroll
        for (int q = 0; q < 4; q++) {
            const float4 v = ((const float4*)xrow)[q];
            const int k = h * 16 + q * 4;
            const float a0 = (v.x - g_stats[k + 0]) * scale;
            const float a1 = (v.y - g_stats[k + 1]) * scale;
            const float a2 = (v.z - g_stats[k + 2]) * scale;
            const float a3 = (v.w - g_stats[k + 3]) * scale;
            xiT[(k + 0) * 128 + r] = a0;
            xiT[(k + 1) * 128 + r] = a1;
            xiT[(k + 2) * 128 + r] = a2;
            xiT[(k + 3) * 128 + r] = a3;
            ps += a0 * a0 + a1 * a1 + a2 * a2 + a3 * a3;
        }
        psqi[t] = ps;
    }
    if (t < 128) {
        const int r = t >> 1, h = t & 1;
        const float* xrow = xe + (size_t)(g * NPG + j0 + r) * EMBD + h * 16;
        float ps = 0.f;
#pragma unroll
        for (int q = 0; q < 4; q++) {
            const float4 v = ((const float4*)xrow)[q];
            const int k = h * 16 + q * 4;
            const float a0 = (v.x - g_stats[k + 0]) * scale;
            const float a1 = (v.y - g_stats[k + 1]) * scale;
            const float a2 = (v.z - g_stats[k + 2]) * scale;
            const float a3 = (v.w - g_stats[k + 3]) * scale;
            xjT[(k + 0) * 64 + r] = a0;
            xjT[(k + 1) * 64 + r] = a1;
            xjT[(k + 2) * 64 + r] = a2;
            xjT[(k + 3) * 64 + r] = a3;
            ps += a0 * a0 + a1 * a1 + a2 * a2 + a3 * a3;
        }
        psqj[t] = ps;
    }
    __syncthreads();
    if (t < 128)        sqi[t]       = psqi[2 * t] + psqi[2 * t + 1];
    else if (t < 192)   sqj[t - 128] = psqj[2 * (t - 128)] + psqj[2 * (t - 128) + 1];
    __syncthreads();

    const int ty = t >> 4, tx = t & 15;
    const int isub = ty * 8, jsub = tx * 4;

    unsigned long long acc[8][2];
#pragma unroll
    for (int r = 0; r < 8; r++) { acc[r][0] = 0ull; acc[r][1] = 0ull; }

#pragma unroll
    for (int k = 0; k < EMBD; k++) {
        const float4 A0 = *(const float4*)&xiT[k * 128 + isub];
        const float4 A1 = *(const float4*)&xiT[k * 128 + isub + 4];
        const float4 B  = *(const float4*)&xjT[k * 64 + jsub];
        const unsigned long long bp0 = pack2(B.x, B.y);
        const unsigned long long bp1 = pack2(B.z, B.w);
        const float av[8] = {A0.x, A0.y, A0.z, A0.w, A1.x, A1.y, A1.z, A1.w};
#pragma unroll
        for (int r = 0; r < 8; r++) {
            const unsigned long long as = pack2(av[r], av[r]);
            acc[r][0] = ffma2(as, bp0, acc[r][0]);
            acc[r][1] = ffma2(as, bp1, acc[r][1]);
        }
    }

    const float temp = *tptr;
    const float athr = fabsf(*thptr);
    const float sj0 = sqj[jsub], sj1 = sqj[jsub + 1];
    const float sj2 = sqj[jsub + 2], sj3 = sqj[jsub + 3];
    const float jbasef = (float)(g * NPG + j0 + jsub);
    const float4 dst4 = make_float4(jbasef, jbasef + 1.f, jbasef + 2.f, jbasef + 3.f);
    const bool write_idx = (g >= G_HELPER);

#pragma unroll
    for (int r = 0; r < 8; r++) {
        const int il = isub + r;
        const float si = sqi[il];
        float d0, d1, d2, d3;
        unpack2(acc[r][0], d0, d1);
        unpack2(acc[r][1], d2, d3);
        const float D0 = fmaxf(si + sj0 - 2.0f * d0, 0.0f);
        const float D1 = fmaxf(si + sj1 - 2.0f * d1, 0.0f);
        const float D2 = fmaxf(si + sj2 - 2.0f * d2, 0.0f);
        const float D3 = fmaxf(si + sj3 - 2.0f * d3, 0.0f);
        float4 A4;
        A4.x = __fdividef(1.0f, 1.0f + __expf(temp * (D0 - athr)));
        A4.y = __fdividef(1.0f, 1.0f + __expf(temp * (D1 - athr)));
        A4.z = __fdividef(1.0f, 1.0f + __expf(temp * (D2 - athr)));
        A4.w = __fdividef(1.0f, 1.0f + __expf(temp * (D3 - athr)));

        const size_t eidx = (size_t)g * ((size_t)NPG * NPG)
                          + (size_t)(i0 + il) * NPG + (size_t)(j0 + jsub);
        st_cs(out + OFF_EW + eidx, A4);
        if (write_idx) {
            const float fsrc = (float)(g * NPG + i0 + il);
            st_cs(out + OFF_SRC + eidx, make_float4(fsrc, fsrc, fsrc, fsrc));
            st_cs(out + OFF_DST + eidx, dst4);
        }
    }
}

// ---------------------------------------------------------------------------
extern "C" void kernel_launch(void* const* d_in, const int* in_sizes, int n_in,
                              void* d_out, int out_size) {
    const float* x     = (const float*)d_in[0];
    const float* W     = (const float*)d_in[1];
    const float* tptr  = (const float*)d_in[2];
    const float* thptr = (const float*)d_in[3];
    float* out = (float*)d_out;

    k1_gemm<<<NTOT / 128, 256>>>(x, W, out);
    k2_stats<<<1, 1024>>>(out);
    k4_pair<<<dim3(16, 8, NG), 256>>>(out, out, tptr, thptr);
}